// round 2
// baseline (speedup 1.0000x reference)
#include <cuda_runtime.h>

typedef unsigned long long ull;
#define NBATCH 4
#define NVERT 512
#define NROWS (NBATCH*NVERT)
#define ABS2 0x7fffffff7fffffffULL

// scratch (allocation-free rule: device globals)
__device__ float g_v [NROWS*64];
__device__ float g_v2[NROWS*64];
__device__ float g_wc[NROWS*64];   // wl_e * c[b,v,e]
__device__ float g_wq[NROWS*64];   // wl_e * qh[b,q,e]
__device__ float g_m [NROWS*64];
__device__ float g_Aw[NROWS];      // sum_e wc
__device__ float g_Bw[NROWS];      // sum_e wq

static __device__ __forceinline__ ull f2add(ull a, ull b){ ull r; asm("add.rn.f32x2 %0,%1,%2;":"=l"(r):"l"(a),"l"(b)); return r; }
static __device__ __forceinline__ ull f2fma(ull a, ull b, ull c){ ull r; asm("fma.rn.f32x2 %0,%1,%2,%3;":"=l"(r):"l"(a),"l"(b),"l"(c)); return r; }
static __device__ __forceinline__ ull fsplat(float x){ ull r; asm("mov.b64 %0,{%1,%1};":"=l"(r):"f"(x)); return r; }
static __device__ __forceinline__ float2 funpack(ull v){ float2 f; asm("mov.b64 {%0,%1},%2;":"=f"(f.x),"=f"(f.y):"l"(v)); return f; }
static __device__ __forceinline__ float lrelu(float x){ return fmaxf(x,0.f) + 0.01f*fminf(x,0.f); }

// ---------------------------------------------------------------------------
// K0: embed  v = vertices @ W_embed + b_embed
// ---------------------------------------------------------------------------
__global__ void __launch_bounds__(256) k_embed(const float* __restrict__ vert,
                                               const float* __restrict__ We,
                                               const float* __restrict__ be)
{
    int idx = blockIdx.x*256 + threadIdx.x;     // 131072 outputs
    int row = idx >> 6, e = idx & 63;
    const float* vr = vert + row*3;
    g_v[idx] = be[e] + vr[0]*We[e] + vr[1]*We[64+e] + vr[2]*We[128+e];
}

// ---------------------------------------------------------------------------
// 16-row x 2-col register-tile GEMM helper over K=64 (weights & inputs in smem)
// ---------------------------------------------------------------------------
static __device__ __forceinline__ void gemm16(const float* __restrict__ W,
                                              const float* __restrict__ inT,
                                              int c0, int r0, float* a0, float* a1)
{
    #pragma unroll
    for (int k=0; k<64; k++){
        float2 w  = *(const float2*)&W[k*66+c0];
        float2 va = *(const float2*)&inT[k*18+r0];
        float2 vb = *(const float2*)&inT[k*18+r0+2];
        a0[0]+=w.x*va.x; a0[1]+=w.x*va.y; a0[2]+=w.x*vb.x; a0[3]+=w.x*vb.y;
        a1[0]+=w.y*va.x; a1[1]+=w.y*va.y; a1[2]+=w.y*vb.x; a1[3]+=w.y*vb.y;
    }
}

// ---------------------------------------------------------------------------
// K1: fused MLP for one block iter.
// h = lrelu(v@Wm+bm+v); v2=v+h; qcm=v2@Wq+bq (q,c,m); qh=q@Wch+bch;
// writes g_v2, g_wc (=wl*c), g_wq (=wl*qh), g_m, g_Aw, g_Bw.
// grid 128 blocks x 128 threads, 16 rows per block.
// ---------------------------------------------------------------------------
__global__ void __launch_bounds__(128) k_mlp(const float* __restrict__ Wm, const float* __restrict__ bm,
                                             const float* __restrict__ Wq, const float* __restrict__ bq,
                                             const float* __restrict__ Wch,const float* __restrict__ bch,
                                             const float* __restrict__ wl)
{
    __shared__ float Wbuf[64*66];
    __shared__ float vT [64*18];
    __shared__ float v2T[64*18];
    __shared__ float qT [64*18];
    __shared__ float wl_s[64];

    const int t = threadIdx.x;
    const int row0 = blockIdx.x*16;

    if (t < 64) wl_s[t] = wl[t];
    for (int i=t; i<1024; i+=128){ int r=i>>6, e=i&63; vT[e*18+r] = g_v[(row0+r)*64+e]; }
    for (int i=t; i<4096; i+=128){ Wbuf[(i>>6)*66+(i&63)] = Wm[i]; }
    __syncthreads();

    const int c0 = (t&31)*2;
    const int r0 = (t>>5)*4;

    // phase 1: h, v2
    {
        float a0[4]={0,0,0,0}, a1[4]={0,0,0,0};
        gemm16(Wbuf, vT, c0, r0, a0, a1);
        float b0=bm[c0], b1=bm[c0+1];
        #pragma unroll
        for (int ri=0; ri<4; ri++){
            int r=r0+ri, row=row0+r;
            float v0=vT[c0*18+r], v1=vT[(c0+1)*18+r];
            float w0=v0+lrelu(a0[ri]+b0+v0);
            float w1=v1+lrelu(a1[ri]+b1+v1);
            v2T[c0*18+r]=w0; v2T[(c0+1)*18+r]=w1;
            *(float2*)&g_v2[row*64+c0] = make_float2(w0,w1);
        }
    }
    __syncthreads();

    // phase 2: qcm = v2@Wq + bq, in 3 column groups (q, c, m)
    for (int g=0; g<3; g++){
        for (int i=t; i<4096; i+=128){ Wbuf[(i>>6)*66+(i&63)] = Wq[(i>>6)*192 + g*64 + (i&63)]; }
        __syncthreads();
        float a0[4]={0,0,0,0}, a1[4]={0,0,0,0};
        gemm16(Wbuf, v2T, c0, r0, a0, a1);
        float b0=bq[g*64+c0], b1=bq[g*64+c0+1];
        #pragma unroll
        for (int ri=0; ri<4; ri++){
            int r=r0+ri, row=row0+r;
            float o0=a0[ri]+b0, o1=a1[ri]+b1;
            if (g==0){ qT[c0*18+r]=o0; qT[(c0+1)*18+r]=o1; }
            else if (g==1){
                float wc0=wl_s[c0]*o0, wc1=wl_s[c0+1]*o1;
                *(float2*)&g_wc[row*64+c0] = make_float2(wc0,wc1);
                float s = wc0+wc1;
                for (int off=16; off; off>>=1) s += __shfl_xor_sync(0xffffffffu, s, off);
                if ((t&31)==0) g_Aw[row]=s;
            } else {
                *(float2*)&g_m[row*64+c0] = make_float2(o0,o1);
            }
        }
        __syncthreads();
    }

    // phase 3: qh = q@Wch + bch
    for (int i=t; i<4096; i+=128){ Wbuf[(i>>6)*66+(i&63)] = Wch[i]; }
    __syncthreads();
    {
        float a0[4]={0,0,0,0}, a1[4]={0,0,0,0};
        gemm16(Wbuf, qT, c0, r0, a0, a1);
        float b0=bch[c0], b1=bch[c0+1];
        #pragma unroll
        for (int ri=0; ri<4; ri++){
            int r=r0+ri, row=row0+r;
            float q0v=a0[ri]+b0, q1v=a1[ri]+b1;
            float wq0=wl_s[c0]*q0v, wq1=wl_s[c0+1]*q1v;
            *(float2*)&g_wq[row*64+c0] = make_float2(wq0,wq1);
            float s = wq0+wq1;
            for (int off=16; off; off>>=1) s += __shfl_xor_sync(0xffffffffu, s, off);
            if ((t&31)==0) g_Bw[row]=s;
        }
    }
}

// ---------------------------------------------------------------------------
// K2: attention for one block iter. 8 q-rows per block, grid (64, B), 256 thr.
// logit(q,v) = 0.505*(Aw_v + Bw_q) + sum_e s2_e*|wc_ve + wq_qe| + bl0
// then mask/temp, softmax over v, heads = probs@m, lrelu, @Wr + br + v2.
// Writes g_v (next iter input) and dout on the final iter.
// ---------------------------------------------------------------------------
__global__ void __launch_bounds__(256) k_attn(float* __restrict__ dout,
    const float* __restrict__ wl, const float* __restrict__ bl,
    const float* __restrict__ Wr, const float* __restrict__ br,
    const float* __restrict__ temp, const float* __restrict__ maskp)
{
    __shared__ float L[8*512];        // logits -> probs
    __shared__ float stage[64*66];    // wc chunk / m chunk / Wr
    __shared__ float wqs[8*66];
    __shared__ float headsS[8*66];
    __shared__ float v2s[8*64];
    __shared__ float s2_s[64], Aws[64], lms[64], Bws[8];

    const int t = threadIdx.x;
    const int b = blockIdx.y;
    const int qg0 = blockIdx.x*8;
    const int rbase = b*NVERT + qg0;

    if (t<64) s2_s[t] = copysignf(0.495f, wl[t]);
    if (t<8)  Bws[t]  = g_Bw[rbase+t];
    for (int i=t; i<512; i+=256){ int r=i>>6, c=i&63;
        wqs[r*66+c] = g_wq[(rbase+r)*64+c];
        v2s[i]      = g_v2[(rbase+r)*64+c];
    }
    const float bl0  = bl[0];
    const float invt = 1.0f/temp[0];

    const int lane = t&31, w = t>>5;
    const int q0 = (w&3)*2;
    const int vl = (w>>2)*32 + lane;

    // ---- pass A: logits ----
    for (int ch=0; ch<8; ch++){
        int vb = ch*64;
        __syncthreads();
        for (int i=t; i<2048; i+=256){ int r=i>>5, c2=(i&31)*2;
            *(float2*)&stage[r*66+c2] = *(const float2*)&g_wc[(b*NVERT+vb+r)*64+c2]; }
        if (t<64){ Aws[t]=g_Aw[b*NVERT+vb+t]; lms[t]=maskp[b*NVERT+vb+t]; }
        __syncthreads();

        const ull* wcv = (const ull*)&stage[vl*66];
        const ull* wqa = (const ull*)&wqs[q0*66];
        const ull* wqb = (const ull*)&wqs[(q0+1)*66];
        const ull* s2p = (const ull*)s2_s;
        ull aA=0, aB=0;
        #pragma unroll
        for (int ep=0; ep<32; ep++){
            ull c = wcv[ep], s = s2p[ep];
            ull t0 = f2add(c, wqa[ep]) & ABS2; aA = f2fma(s, t0, aA);
            ull t1 = f2add(c, wqb[ep]) & ABS2; aB = f2fma(s, t1, aB);
        }
        float2 fA=funpack(aA), fB=funpack(aB);
        float base = 0.505f*Aws[vl] + bl0;
        float lm = lms[vl];
        float lA = base + 0.505f*Bws[q0]   + fA.x + fA.y;
        float lB = base + 0.505f*Bws[q0+1] + fB.x + fB.y;
        L[ q0   *512 + vb + vl] = lA*invt*lm - 99999.f*(1.f-lm);
        L[(q0+1)*512 + vb + vl] = lB*invt*lm - 99999.f*(1.f-lm);
    }
    __syncthreads();

    // ---- pass B: softmax per q-row (warp w handles row w) ----
    {
        float lv[16];
        #pragma unroll
        for (int j=0;j<16;j++) lv[j] = L[w*512 + lane + 32*j];
        float mx = lv[0];
        #pragma unroll
        for (int j=1;j<16;j++) mx = fmaxf(mx, lv[j]);
        for (int off=16; off; off>>=1) mx = fmaxf(mx, __shfl_xor_sync(0xffffffffu, mx, off));
        float ev[16], ssum=0.f;
        #pragma unroll
        for (int j=0;j<16;j++){ ev[j] = expf(lv[j]-mx); ssum += ev[j]; }
        for (int off=16; off; off>>=1) ssum += __shfl_xor_sync(0xffffffffu, ssum, off);
        float inv = 1.0f/ssum;
        #pragma unroll
        for (int j=0;j<16;j++){
            float lm = maskp[b*NVERT + lane + 32*j];
            L[w*512 + lane + 32*j] = ev[j]*inv*lm;
        }
    }
    __syncthreads();

    // ---- pass C: heads = probs @ m  (thread = (q=w, e-pair=lane)) ----
    ull hacc = 0;
    for (int ch=0; ch<8; ch++){
        int vb = ch*64;
        for (int i=t; i<2048; i+=256){ int r=i>>5, c2=(i&31)*2;
            *(float2*)&stage[r*66+c2] = *(const float2*)&g_m[(b*NVERT+vb+r)*64+c2]; }
        __syncthreads();
        const float* Lq = &L[w*512 + vb];
        #pragma unroll
        for (int v=0; v<64; v+=4){
            float4 p = *(const float4*)&Lq[v];
            hacc = f2fma(fsplat(p.x), *(const ull*)&stage[(v+0)*66+2*lane], hacc);
            hacc = f2fma(fsplat(p.y), *(const ull*)&stage[(v+1)*66+2*lane], hacc);
            hacc = f2fma(fsplat(p.z), *(const ull*)&stage[(v+2)*66+2*lane], hacc);
            hacc = f2fma(fsplat(p.w), *(const ull*)&stage[(v+3)*66+2*lane], hacc);
        }
        __syncthreads();
    }
    {
        float2 h = funpack(hacc);
        headsS[w*66+2*lane]   = lrelu(h.x);
        headsS[w*66+2*lane+1] = lrelu(h.y);
    }
    // stage Wr (64x64)
    for (int i=t; i<2048; i+=256){ int r=i>>5, c2=(i&31)*2;
        *(float2*)&stage[r*66+c2] = *(const float2*)&Wr[r*64+c2]; }
    __syncthreads();

    // ---- out = lrelu(heads) @ Wr + br + v2 ----
    ull oacc = 0;
    #pragma unroll 8
    for (int e=0; e<64; e++)
        oacc = f2fma(fsplat(headsS[w*66+e]), *(const ull*)&stage[e*66+2*lane], oacc);
    float2 o = funpack(oacc);
    int row = rbase + w, col = 2*lane;
    float r0v = o.x + br[col]   + v2s[w*64+col];
    float r1v = o.y + br[col+1] + v2s[w*64+col+1];
    g_v[row*64+col]   = r0v;
    g_v[row*64+col+1] = r1v;
    if (dout){
        dout[row*64+col]   = r0v;
        dout[row*64+col+1] = r1v;
    }
}

// ---------------------------------------------------------------------------
extern "C" void kernel_launch(void* const* d_in, const int* in_sizes, int n_in,
                              void* d_out, int out_size)
{
    const float* vertices = (const float*)d_in[0];
    const float* mask     = (const float*)d_in[1];
    const float* W_embed  = (const float*)d_in[2];
    const float* b_embed  = (const float*)d_in[3];
    const float* W_mlp    = (const float*)d_in[4];
    const float* b_mlp    = (const float*)d_in[5];
    const float* W_qcm    = (const float*)d_in[6];
    const float* b_qcm    = (const float*)d_in[7];
    const float* W_ch     = (const float*)d_in[8];
    const float* b_ch     = (const float*)d_in[9];
    const float* W_logit  = (const float*)d_in[10];
    const float* b_logit  = (const float*)d_in[11];
    const float* W_red    = (const float*)d_in[12];
    const float* b_red    = (const float*)d_in[13];
    const float* temp     = (const float*)d_in[14];
    float* out = (float*)d_out;

    k_embed<<<512,256>>>(vertices, W_embed, b_embed);
    for (int i=0; i<3; i++){
        k_mlp<<<128,128>>>(W_mlp + i*4096, b_mlp + i*64,
                           W_qcm + i*12288, b_qcm + i*192,
                           W_ch  + i*4096, b_ch  + i*64,
                           W_logit + i*64);
        k_attn<<<dim3(64,4),256>>>(i==2 ? out : (float*)nullptr,
                                   W_logit + i*64, b_logit + i,
                                   W_red + i*4096, b_red + i*64,
                                   temp + i, mask);
    }
}

// round 3
// speedup vs baseline: 1.4263x; 1.4263x over previous
#include <cuda_runtime.h>

typedef unsigned long long ull;
#define NBATCH 4
#define NVERT 512
#define NROWS (NBATCH*NVERT)
#define ABS2 0x7fffffff7fffffffULL

// scratch (allocation-free rule: device globals)
__device__ float g_v [NROWS*64];
__device__ float g_v2[NROWS*64];
__device__ float g_wc[NROWS*64];   // wl_e * c[b,v,e]
__device__ float g_wq[NROWS*64];   // wl_e * qh[b,q,e]
__device__ float g_m [NROWS*64];
__device__ float g_Aw[NROWS];      // sum_e wc
__device__ float g_Bw[NROWS];      // sum_e wq

static __device__ __forceinline__ ull f2add(ull a, ull b){ ull r; asm("add.rn.f32x2 %0,%1,%2;":"=l"(r):"l"(a),"l"(b)); return r; }
static __device__ __forceinline__ ull f2fma(ull a, ull b, ull c){ ull r; asm("fma.rn.f32x2 %0,%1,%2,%3;":"=l"(r):"l"(a),"l"(b),"l"(c)); return r; }
static __device__ __forceinline__ ull fsplat(float x){ ull r; asm("mov.b64 %0,{%1,%1};":"=l"(r):"f"(x)); return r; }
static __device__ __forceinline__ float2 funpack(ull v){ float2 f; asm("mov.b64 {%0,%1},%2;":"=f"(f.x),"=f"(f.y):"l"(v)); return f; }
static __device__ __forceinline__ float lrelu(float x){ return fmaxf(x,0.f) + 0.01f*fminf(x,0.f); }

// ---------------------------------------------------------------------------
// K0: embed  v = vertices @ W_embed + b_embed
// ---------------------------------------------------------------------------
__global__ void __launch_bounds__(256) k_embed(const float* __restrict__ vert,
                                               const float* __restrict__ We,
                                               const float* __restrict__ be)
{
    int idx = blockIdx.x*256 + threadIdx.x;
    int row = idx >> 6, e = idx & 63;
    const float* vr = vert + row*3;
    g_v[idx] = be[e] + vr[0]*We[e] + vr[1]*We[64+e] + vr[2]*We[128+e];
}

// ---------------------------------------------------------------------------
// K1: fused MLP. 8 rows/block, 256 blocks x 256 threads.
// All weights staged ONCE in dynamic smem (stride 66, conflict-free).
// thread: r = t>>5 (row), c0 = (t&31)*2 (col pair).
// ---------------------------------------------------------------------------
#define MLP_SMEM_FLOATS (5*4224 + 3*512 + 64)

__global__ void __launch_bounds__(256) k_mlp(const float* __restrict__ Wm, const float* __restrict__ bm,
                                             const float* __restrict__ Wq, const float* __restrict__ bq,
                                             const float* __restrict__ Wch,const float* __restrict__ bch,
                                             const float* __restrict__ wl)
{
    extern __shared__ float sm[];
    float* Wm_s  = sm;                 // 64*66
    float* Wq_s  = sm + 4224;          // 3 * 64*66
    float* Wch_s = sm + 4*4224;        // 64*66
    float* vT    = sm + 5*4224;        // 8*64 [r][k]
    float* v2T   = vT + 512;
    float* qT    = v2T + 512;
    float* wl_s  = qT + 512;

    const int t = threadIdx.x;
    const int row0 = blockIdx.x*8;

    // stage weights + inputs (float2)
    for (int i=t; i<2048; i+=256){ int k=i>>5, c2=(i&31)*2;
        *(float2*)&Wm_s [k*66+c2] = *(const float2*)&Wm [k*64+c2];
        *(float2*)&Wch_s[k*66+c2] = *(const float2*)&Wch[k*64+c2]; }
    for (int i=t; i<6144; i+=256){ int k=i/96, rem=i-k*96; int g=rem>>5, c2=(rem&31)*2;
        *(float2*)&Wq_s[g*4224 + k*66 + c2] = *(const float2*)&Wq[k*192 + g*64 + c2]; }
    for (int i=t; i<256; i+=256){ int r=i>>5, c2=(i&31)*2;
        *(float2*)&vT[r*64+c2] = *(const float2*)&g_v[(row0+r)*64+c2]; }
    if (t<64) wl_s[t] = wl[t];
    __syncthreads();

    const int c0 = (t&31)*2;
    const int r  = t>>5;
    const int row = row0 + r;

    // phase 1: h = lrelu(v@Wm+bm+v); v2 = v+h
    {
        float a0=0.f, a1=0.f;
        #pragma unroll
        for (int k=0;k<64;k++){
            float2 w = *(const float2*)&Wm_s[k*66+c0];
            float vv = vT[r*64+k];
            a0 += vv*w.x; a1 += vv*w.y;
        }
        float b0=__ldg(&bm[c0]), b1=__ldg(&bm[c0+1]);
        float v0=vT[r*64+c0], v1=vT[r*64+c0+1];
        float w0 = v0 + lrelu(a0+b0+v0);
        float w1 = v1 + lrelu(a1+b1+v1);
        v2T[r*64+c0]=w0; v2T[r*64+c0+1]=w1;
        *(float2*)&g_v2[row*64+c0] = make_float2(w0,w1);
    }
    __syncthreads();

    // phase 2: qcm = v2@Wq + bq  (3 groups fused: q, c, m)
    {
        float a[6]={0,0,0,0,0,0};
        #pragma unroll
        for (int k=0;k<64;k++){
            float vv = v2T[r*64+k];
            float2 w0 = *(const float2*)&Wq_s[        k*66+c0];
            float2 w1 = *(const float2*)&Wq_s[4224  + k*66+c0];
            float2 w2 = *(const float2*)&Wq_s[2*4224+ k*66+c0];
            a[0]+=vv*w0.x; a[1]+=vv*w0.y;
            a[2]+=vv*w1.x; a[3]+=vv*w1.y;
            a[4]+=vv*w2.x; a[5]+=vv*w2.y;
        }
        // group 0: q -> qT
        qT[r*64+c0]   = a[0]+__ldg(&bq[c0]);
        qT[r*64+c0+1] = a[1]+__ldg(&bq[c0+1]);
        // group 1: c -> wc = wl*c, Aw = row-sum
        {
            float o0=a[2]+__ldg(&bq[64+c0]), o1=a[3]+__ldg(&bq[64+c0+1]);
            float wc0=wl_s[c0]*o0, wc1=wl_s[c0+1]*o1;
            *(float2*)&g_wc[row*64+c0] = make_float2(wc0,wc1);
            float s=wc0+wc1;
            for (int off=16; off; off>>=1) s += __shfl_xor_sync(0xffffffffu, s, off);
            if ((t&31)==0) g_Aw[row]=s;
        }
        // group 2: m
        *(float2*)&g_m[row*64+c0] = make_float2(a[4]+__ldg(&bq[128+c0]), a[5]+__ldg(&bq[128+c0+1]));
    }
    __syncthreads();

    // phase 3: qh = q@Wch + bch -> wq = wl*qh, Bw = row-sum
    {
        float a0=0.f, a1=0.f;
        #pragma unroll
        for (int k=0;k<64;k++){
            float2 w = *(const float2*)&Wch_s[k*66+c0];
            float vv = qT[r*64+k];
            a0 += vv*w.x; a1 += vv*w.y;
        }
        float q0v=a0+__ldg(&bch[c0]), q1v=a1+__ldg(&bch[c0+1]);
        float wq0=wl_s[c0]*q0v, wq1=wl_s[c0+1]*q1v;
        *(float2*)&g_wq[row*64+c0] = make_float2(wq0,wq1);
        float s=wq0+wq1;
        for (int off=16; off; off>>=1) s += __shfl_xor_sync(0xffffffffu, s, off);
        if ((t&31)==0) g_Bw[row]=s;
    }
}

// ---------------------------------------------------------------------------
// K2: attention. 8 q-rows/block, grid (64, B) = 256 blocks, 256 threads.
// Pass A: logits with 4q x 2v register tile over 256-v staged halves.
// Pass B: softmax (warp per q-row).
// Pass C: heads = probs@m, 4q-per-thread tile.
// Final: lrelu(heads)@Wr + br + v2.
// ---------------------------------------------------------------------------
#define ATTN_SMEM_FLOATS (16896 + 4096 + 512 + 512 + 528 + 512 + 64 + 8 + 528 + 2048)

__global__ void __launch_bounds__(256) k_attn(float* __restrict__ dout,
    const float* __restrict__ wl, const float* __restrict__ bl,
    const float* __restrict__ Wr, const float* __restrict__ br,
    const float* __restrict__ temp, const float* __restrict__ maskp)
{
    extern __shared__ float sm[];
    float* stage = sm;                    // 256*66 : wc halves / m halves / Wr
    float* L     = sm + 16896;            // 8*512
    float* Aws   = L + 4096;              // 512
    float* lms   = Aws + 512;             // 512
    float* wqs   = lms + 512;             // 8*66
    float* v2s   = wqs + 528;             // 8*64
    float* s2s   = v2s + 512;             // 64
    float* Bws   = s2s + 64;              // 8
    float* heads = Bws + 8;               // 8*66
    ull*   hpart = (ull*)(heads + 528);   // 4*2*32*4 = 1024 ull

    const int t = threadIdx.x;
    const int b = blockIdx.y;
    const int rbase = b*NVERT + blockIdx.x*8;

    // ---- initial staging ----
    if (t<64) s2s[t] = copysignf(0.495f, __ldg(&wl[t]));
    if (t<8)  Bws[t] = g_Bw[rbase+t];
    for (int i=t; i<512; i+=256){ Aws[i]=g_Aw[b*NVERT+i]; lms[i]=__ldg(&maskp[b*NVERT+i]); }
    for (int i=t; i<256; i+=256){ int r=i>>5, c2=(i&31)*2;
        *(float2*)&wqs[r*66+c2] = *(const float2*)&g_wq[(rbase+r)*64+c2];
        *(float2*)&v2s[r*64+c2] = *(const float2*)&g_v2[(rbase+r)*64+c2]; }
    const float bl0  = __ldg(&bl[0]);
    const float invt = 1.0f/__ldg(&temp[0]);

    // ---- pass A: logits, two 256-v halves ----
    const int qt = t>>7;            // 0..1
    const int q0 = qt*4;
    const int vl = t&127;           // local v (pairs with vl+128)

    for (int h=0; h<2; h++){
        for (int i=t; i<8192; i+=256){ int r=i>>5, c2=(i&31)*2;
            *(float2*)&stage[r*66+c2] = *(const float2*)&g_wc[(b*NVERT + h*256 + r)*64 + c2]; }
        __syncthreads();

        const ull* pc0 = (const ull*)&stage[ vl      *66];
        const ull* pc1 = (const ull*)&stage[(vl+128) *66];
        const ull* pq0 = (const ull*)&wqs[(q0+0)*66];
        const ull* pq1 = (const ull*)&wqs[(q0+1)*66];
        const ull* pq2 = (const ull*)&wqs[(q0+2)*66];
        const ull* pq3 = (const ull*)&wqs[(q0+3)*66];
        const ull* s2p = (const ull*)s2s;

        ull a[8] = {0,0,0,0,0,0,0,0};
        #pragma unroll 8
        for (int ep=0; ep<32; ep++){
            ull cA = pc0[ep], cB = pc1[ep], s = s2p[ep];
            ull w0 = pq0[ep], w1 = pq1[ep], w2 = pq2[ep], w3 = pq3[ep];
            a[0] = f2fma(s, f2add(cA,w0)&ABS2, a[0]);
            a[1] = f2fma(s, f2add(cB,w0)&ABS2, a[1]);
            a[2] = f2fma(s, f2add(cA,w1)&ABS2, a[2]);
            a[3] = f2fma(s, f2add(cB,w1)&ABS2, a[3]);
            a[4] = f2fma(s, f2add(cA,w2)&ABS2, a[4]);
            a[5] = f2fma(s, f2add(cB,w2)&ABS2, a[5]);
            a[6] = f2fma(s, f2add(cA,w3)&ABS2, a[6]);
            a[7] = f2fma(s, f2add(cB,w3)&ABS2, a[7]);
        }
        #pragma unroll
        for (int i=0;i<4;i++){
            #pragma unroll
            for (int j=0;j<2;j++){
                float2 f = funpack(a[i*2+j]);
                int vg = h*256 + (j? vl+128 : vl);
                float lg = 0.505f*(Aws[vg] + Bws[q0+i]) + bl0 + f.x + f.y;
                float lm = lms[vg];
                L[(q0+i)*512 + vg] = lg*invt*lm - 99999.f*(1.f-lm);
            }
        }
        __syncthreads();
    }

    // ---- pass B: softmax (warp w handles q-row w) ----
    {
        const int lane = t&31, w = t>>5;
        float lv[16];
        #pragma unroll
        for (int j=0;j<16;j++) lv[j] = L[w*512 + lane + 32*j];
        float mx = lv[0];
        #pragma unroll
        for (int j=1;j<16;j++) mx = fmaxf(mx, lv[j]);
        for (int off=16; off; off>>=1) mx = fmaxf(mx, __shfl_xor_sync(0xffffffffu, mx, off));
        float ev[16], ssum=0.f;
        #pragma unroll
        for (int j=0;j<16;j++){ ev[j] = __expf(lv[j]-mx); ssum += ev[j]; }
        for (int off=16; off; off>>=1) ssum += __shfl_xor_sync(0xffffffffu, ssum, off);
        float inv = 1.0f/ssum;
        #pragma unroll
        for (int j=0;j<16;j++) L[w*512 + lane + 32*j] = ev[j]*inv*lms[lane+32*j];
    }
    __syncthreads();

    // ---- pass C: heads = probs @ m.  thread = (qg, sr, ep) ----
    const int ep  = t&31;
    const int sr  = (t>>5)&3;     // 64-v subrange
    const int qg  = t>>7;         // q group of 4
    ull acc[4] = {0,0,0,0};

    for (int h=0; h<2; h++){
        for (int i=t; i<8192; i+=256){ int r=i>>5, c2=(i&31)*2;
            *(float2*)&stage[r*66+c2] = *(const float2*)&g_m[(b*NVERT + h*256 + r)*64 + c2]; }
        __syncthreads();
        const float* L0 = &L[(qg*4+0)*512 + h*256 + sr*64];
        const float* L1 = &L[(qg*4+1)*512 + h*256 + sr*64];
        const float* L2 = &L[(qg*4+2)*512 + h*256 + sr*64];
        const float* L3 = &L[(qg*4+3)*512 + h*256 + sr*64];
        #pragma unroll 4
        for (int vv=0; vv<64; vv++){
            ull mv = *(const ull*)&stage[(sr*64+vv)*66 + 2*ep];
            acc[0] = f2fma(fsplat(L0[vv]), mv, acc[0]);
            acc[1] = f2fma(fsplat(L1[vv]), mv, acc[1]);
            acc[2] = f2fma(fsplat(L2[vv]), mv, acc[2]);
            acc[3] = f2fma(fsplat(L3[vv]), mv, acc[3]);
        }
        __syncthreads();
    }
    #pragma unroll
    for (int i=0;i<4;i++) hpart[((sr*2+qg)*32+ep)*4+i] = acc[i];
    __syncthreads();

    // combine partials -> heads (lrelu applied), stage Wr
    {
        const int tq = t>>5, tep = t&31;
        const int hqg = tq>>2, hi = tq&3;
        ull s = f2add(f2add(hpart[((0*2+hqg)*32+tep)*4+hi], hpart[((1*2+hqg)*32+tep)*4+hi]),
                      f2add(hpart[((2*2+hqg)*32+tep)*4+hi], hpart[((3*2+hqg)*32+tep)*4+hi]));
        float2 hv = funpack(s);
        heads[tq*66+2*tep]   = lrelu(hv.x);
        heads[tq*66+2*tep+1] = lrelu(hv.y);
    }
    for (int i=t; i<2048; i+=256){ int e=i>>5, c2=(i&31)*2;
        *(float2*)&stage[e*66+c2] = *(const float2*)&Wr[e*64+c2]; }
    __syncthreads();

    // ---- final: out = lrelu(heads)@Wr + br + v2 ----
    {
        const int q = t>>5, c0 = (t&31)*2;
        ull oacc = 0;
        #pragma unroll 8
        for (int e=0; e<64; e++)
            oacc = f2fma(fsplat(heads[q*66+e]), *(const ull*)&stage[e*66+c0], oacc);
        float2 o = funpack(oacc);
        int row = rbase + q;
        float r0v = o.x + __ldg(&br[c0])   + v2s[q*64+c0];
        float r1v = o.y + __ldg(&br[c0+1]) + v2s[q*64+c0+1];
        *(float2*)&g_v[row*64+c0] = make_float2(r0v, r1v);
        if (dout) *(float2*)&dout[row*64+c0] = make_float2(r0v, r1v);
    }
}

// ---------------------------------------------------------------------------
extern "C" void kernel_launch(void* const* d_in, const int* in_sizes, int n_in,
                              void* d_out, int out_size)
{
    const float* vertices = (const float*)d_in[0];
    const float* mask     = (const float*)d_in[1];
    const float* W_embed  = (const float*)d_in[2];
    const float* b_embed  = (const float*)d_in[3];
    const float* W_mlp    = (const float*)d_in[4];
    const float* b_mlp    = (const float*)d_in[5];
    const float* W_qcm    = (const float*)d_in[6];
    const float* b_qcm    = (const float*)d_in[7];
    const float* W_ch     = (const float*)d_in[8];
    const float* b_ch     = (const float*)d_in[9];
    const float* W_logit  = (const float*)d_in[10];
    const float* b_logit  = (const float*)d_in[11];
    const float* W_red    = (const float*)d_in[12];
    const float* b_red    = (const float*)d_in[13];
    const float* temp     = (const float*)d_in[14];
    float* out = (float*)d_out;

    const int mlp_smem  = MLP_SMEM_FLOATS*4;
    const int attn_smem = ATTN_SMEM_FLOATS*4;
    cudaFuncSetAttribute(k_mlp,  cudaFuncAttributeMaxDynamicSharedMemorySize, mlp_smem);
    cudaFuncSetAttribute(k_attn, cudaFuncAttributeMaxDynamicSharedMemorySize, attn_smem);

    k_embed<<<512,256>>>(vertices, W_embed, b_embed);
    for (int i=0; i<3; i++){
        k_mlp<<<256,256,mlp_smem>>>(W_mlp + i*4096, b_mlp + i*64,
                                    W_qcm + i*12288, b_qcm + i*192,
                                    W_ch  + i*4096, b_ch  + i*64,
                                    W_logit + i*64);
        k_attn<<<dim3(64,NBATCH),256,attn_smem>>>(i==2 ? out : (float*)nullptr,
                                                  W_logit + i*64, b_logit + i,
                                                  W_red + i*4096, b_red + i*64,
                                                  temp + i, mask);
    }
}

// round 4
// speedup vs baseline: 1.8442x; 1.2930x over previous
#include <cuda_runtime.h>

typedef unsigned long long ull;
#define NBATCH 4
#define NVERT 512
#define NROWS (NBATCH*NVERT)
#define ABS2 0x7fffffff7fffffffULL

// scratch (allocation-free rule: device globals)
__device__ float g_v [NROWS*64];
__device__ float g_v2[NROWS*64];
__device__ float g_wc[NROWS*64];   // wl_e * c[b,v,e]
__device__ float g_wq[NROWS*64];   // wl_e * qh[b,q,e]
__device__ float g_m [NROWS*64];
__device__ float g_Aw[NROWS];      // sum_e wc
__device__ float g_Bw[NROWS];      // sum_e wq

static __device__ __forceinline__ ull f2add(ull a, ull b){ ull r; asm("add.rn.f32x2 %0,%1,%2;":"=l"(r):"l"(a),"l"(b)); return r; }
static __device__ __forceinline__ ull f2fma(ull a, ull b, ull c){ ull r; asm("fma.rn.f32x2 %0,%1,%2,%3;":"=l"(r):"l"(a),"l"(b),"l"(c)); return r; }
static __device__ __forceinline__ ull fsplat(float x){ ull r; asm("mov.b64 %0,{%1,%1};":"=l"(r):"f"(x)); return r; }
static __device__ __forceinline__ float2 funpack(ull v){ float2 f; asm("mov.b64 {%0,%1},%2;":"=f"(f.x),"=f"(f.y):"l"(v)); return f; }
static __device__ __forceinline__ float lrelu(float x){ return fmaxf(x,0.f) + 0.01f*fminf(x,0.f); }

static __device__ __forceinline__ unsigned sa(const void* p){
    unsigned a; asm("{ .reg .u64 t0; cvta.to.shared.u64 t0, %1; cvt.u32.u64 %0, t0; }":"=r"(a):"l"(p)); return a; }
#define CPA8(d,s) asm volatile("cp.async.ca.shared.global [%0], [%1], 8;"::"r"(sa(d)),"l"(s))
#define CPAC()  asm volatile("cp.async.commit_group;")
#define CPAW0() asm volatile("cp.async.wait_group 0;")
#define CPAW1() asm volatile("cp.async.wait_group 1;")

// ---------------------------------------------------------------------------
// K1: fused MLP (+embed on iter0). 16 rows/block, 128 blocks x 256 threads.
// thread tile: 2 rows x 2 cols. Weights staged via cp.async (stride 66).
// ---------------------------------------------------------------------------
#define MLPS (5*4224 + 3*1024 + 64)

__global__ void __launch_bounds__(256) k_mlp(
    const float* __restrict__ vert, const float* __restrict__ We, const float* __restrict__ be,
    const float* __restrict__ Wm, const float* __restrict__ bm,
    const float* __restrict__ Wq, const float* __restrict__ bq,
    const float* __restrict__ Wch,const float* __restrict__ bch,
    const float* __restrict__ wl)
{
    extern __shared__ float sm[];
    float* Wm_s = sm;                 // 64*66
    float* Wq_s = sm + 4224;          // 3*64*66
    float* Wch_s= sm + 4*4224;        // 64*66
    float* vS   = sm + 5*4224;        // 16*64
    float* v2S  = vS + 1024;          // 16*64
    float* qS   = v2S + 1024;         // 16*64
    float* wl_s = qS + 1024;          // 64

    const int t = threadIdx.x;
    const int row0 = blockIdx.x*16;

    // group 0: Wm, wl, v (cp.async)
    #pragma unroll
    for (int j=0;j<8;j++){ int p=t+j*256, k=p>>5, c=(p&31)*2; CPA8(&Wm_s[k*66+c], &Wm[k*64+c]); }
    if (t<32) CPA8(&wl_s[2*t], &wl[2*t]);
    if (!vert){
        #pragma unroll
        for (int j=0;j<2;j++){ int p=t+j*256, r=p>>5, c=(p&31)*2; CPA8(&vS[r*64+c], &g_v[(row0+r)*64+c]); }
    }
    CPAC();
    // group 1: Wq (3 groups), Wch
    #pragma unroll
    for (int g=0; g<3; g++)
        #pragma unroll
        for (int j=0;j<8;j++){ int p=t+j*256, k=p>>5, c=(p&31)*2; CPA8(&Wq_s[g*4224+k*66+c], &Wq[k*192+g*64+c]); }
    #pragma unroll
    for (int j=0;j<8;j++){ int p=t+j*256, k=p>>5, c=(p&31)*2; CPA8(&Wch_s[k*66+c], &Wch[k*64+c]); }
    CPAC();

    if (vert){  // iter 0: compute embed directly into vS
        #pragma unroll
        for (int j=0;j<2;j++){
            int p=t+j*256, r=p>>5, c=(p&31)*2; int row=row0+r;
            float x=__ldg(&vert[row*3]), y=__ldg(&vert[row*3+1]), z=__ldg(&vert[row*3+2]);
            vS[r*64+c]   = __ldg(&be[c])   + x*__ldg(&We[c])   + y*__ldg(&We[64+c])   + z*__ldg(&We[128+c]);
            vS[r*64+c+1] = __ldg(&be[c+1]) + x*__ldg(&We[c+1]) + y*__ldg(&We[64+c+1]) + z*__ldg(&We[128+c+1]);
        }
    }
    CPAW1(); __syncthreads();   // Wm, wl, v ready

    const int r0 = (t>>5)*2, r1 = r0+1, c0 = (t&31)*2;
    const int rowA = row0 + r0, rowB = row0 + r1;

    // ---- phase 1: h = lrelu(v@Wm+bm+v); v2 = v+h ----
    {
        float a00=0,a01=0,a10=0,a11=0;
        #pragma unroll
        for (int k=0;k<64;k++){
            float2 w = *(const float2*)&Wm_s[k*66+c0];
            float vA = vS[r0*64+k], vB = vS[r1*64+k];
            a00 += vA*w.x; a01 += vA*w.y; a10 += vB*w.x; a11 += vB*w.y;
        }
        float b0=__ldg(&bm[c0]), b1=__ldg(&bm[c0+1]);
        float xA0=vS[r0*64+c0], xA1=vS[r0*64+c0+1], xB0=vS[r1*64+c0], xB1=vS[r1*64+c0+1];
        float v2A0 = xA0 + lrelu(a00+b0+xA0);
        float v2A1 = xA1 + lrelu(a01+b1+xA1);
        float v2B0 = xB0 + lrelu(a10+b0+xB0);
        float v2B1 = xB1 + lrelu(a11+b1+xB1);
        v2S[r0*64+c0]=v2A0; v2S[r0*64+c0+1]=v2A1;
        v2S[r1*64+c0]=v2B0; v2S[r1*64+c0+1]=v2B1;
        *(float2*)&g_v2[rowA*64+c0] = make_float2(v2A0,v2A1);
        *(float2*)&g_v2[rowB*64+c0] = make_float2(v2B0,v2B1);
    }
    CPAW0(); __syncthreads();   // Wq/Wch staged by all threads; v2S visible

    // ---- phase 2: qcm = v2@Wq + bq, 3 groups fused (12 accumulators) ----
    {
        float aq0A=0,aq1A=0,aq0B=0,aq1B=0, ac0A=0,ac1A=0,ac0B=0,ac1B=0, am0A=0,am1A=0,am0B=0,am1B=0;
        #pragma unroll 8
        for (int k=0;k<64;k++){
            float vA = v2S[r0*64+k], vB = v2S[r1*64+k];
            float2 wq_ = *(const float2*)&Wq_s[       k*66+c0];
            float2 wc_ = *(const float2*)&Wq_s[4224 + k*66+c0];
            float2 wm_ = *(const float2*)&Wq_s[8448 + k*66+c0];
            aq0A+=vA*wq_.x; aq1A+=vA*wq_.y; aq0B+=vB*wq_.x; aq1B+=vB*wq_.y;
            ac0A+=vA*wc_.x; ac1A+=vA*wc_.y; ac0B+=vB*wc_.x; ac1B+=vB*wc_.y;
            am0A+=vA*wm_.x; am1A+=vA*wm_.y; am0B+=vB*wm_.x; am1B+=vB*wm_.y;
        }
        float bq0=__ldg(&bq[c0]), bq1=__ldg(&bq[c0+1]);
        qS[r0*64+c0]=aq0A+bq0; qS[r0*64+c0+1]=aq1A+bq1;
        qS[r1*64+c0]=aq0B+bq0; qS[r1*64+c0+1]=aq1B+bq1;

        float bc0=__ldg(&bq[64+c0]), bc1=__ldg(&bq[64+c0+1]);
        float wl0=wl_s[c0], wl1=wl_s[c0+1];
        float wcA0=wl0*(ac0A+bc0), wcA1=wl1*(ac1A+bc1);
        float wcB0=wl0*(ac0B+bc0), wcB1=wl1*(ac1B+bc1);
        *(float2*)&g_wc[rowA*64+c0] = make_float2(wcA0,wcA1);
        *(float2*)&g_wc[rowB*64+c0] = make_float2(wcB0,wcB1);
        float sA=wcA0+wcA1, sB=wcB0+wcB1;
        for (int off=16; off; off>>=1){ sA += __shfl_xor_sync(~0u,sA,off); sB += __shfl_xor_sync(~0u,sB,off); }
        if ((t&31)==0){ g_Aw[rowA]=sA; g_Aw[rowB]=sB; }

        float bmm0=__ldg(&bq[128+c0]), bmm1=__ldg(&bq[128+c0+1]);
        *(float2*)&g_m[rowA*64+c0] = make_float2(am0A+bmm0, am1A+bmm1);
        *(float2*)&g_m[rowB*64+c0] = make_float2(am0B+bmm0, am1B+bmm1);
    }
    __syncwarp();   // qS rows are warp-private

    // ---- phase 3: qh = q@Wch + bch -> wq = wl*qh, Bw = row-sum ----
    {
        float a00=0,a01=0,a10=0,a11=0;
        #pragma unroll
        for (int k=0;k<64;k++){
            float2 w = *(const float2*)&Wch_s[k*66+c0];
            float qA = qS[r0*64+k], qB = qS[r1*64+k];
            a00 += qA*w.x; a01 += qA*w.y; a10 += qB*w.x; a11 += qB*w.y;
        }
        float b0=__ldg(&bch[c0]), b1=__ldg(&bch[c0+1]);
        float wl0=wl_s[c0], wl1=wl_s[c0+1];
        float wqA0=wl0*(a00+b0), wqA1=wl1*(a01+b1);
        float wqB0=wl0*(a10+b0), wqB1=wl1*(a11+b1);
        *(float2*)&g_wq[rowA*64+c0] = make_float2(wqA0,wqA1);
        *(float2*)&g_wq[rowB*64+c0] = make_float2(wqB0,wqB1);
        float sA=wqA0+wqA1, sB=wqB0+wqB1;
        for (int off=16; off; off>>=1){ sA += __shfl_xor_sync(~0u,sA,off); sB += __shfl_xor_sync(~0u,sB,off); }
        if ((t&31)==0){ g_Bw[rowA]=sA; g_Bw[rowB]=sB; }
    }
}

// ---------------------------------------------------------------------------
// K2: attention. 8 q-rows/block, grid (64, B), 256 threads, cp.async staging.
// ---------------------------------------------------------------------------
#define ATTNS (16896 + 4096 + 512 + 512 + 528 + 512 + 64 + 8 + 528 + 2048)

__global__ void __launch_bounds__(256) k_attn(float* __restrict__ dout,
    const float* __restrict__ wl, const float* __restrict__ bl,
    const float* __restrict__ Wr, const float* __restrict__ br,
    const float* __restrict__ temp, const float* __restrict__ maskp)
{
    extern __shared__ float sm[];
    float* stage = sm;                    // 256*66 : wc halves / m halves / Wr
    float* L     = sm + 16896;            // 8*512
    float* Aws   = L + 4096;              // 512
    float* lms   = Aws + 512;             // 512
    float* wqs   = lms + 512;             // 8*66
    float* v2s   = wqs + 528;             // 8*64
    float* s2s   = v2s + 512;             // 64
    float* Bws   = s2s + 64;              // 8
    float* heads = Bws + 8;               // 8*66
    ull*   hpart = (ull*)(heads + 528);   // 1024 ull

    const int t = threadIdx.x;
    const int b = blockIdx.y;
    const int rbase = b*NVERT + blockIdx.x*8;

    // ---- initial staging (all cp.async, one group) ----
    { int r=t>>5, c=(t&31)*2;
      CPA8(&wqs[r*66+c], &g_wq[(rbase+r)*64+c]);
      CPA8(&v2s[r*64+c], &g_v2[(rbase+r)*64+c]); }
    CPA8(&Aws[2*t], &g_Aw[b*NVERT+2*t]);
    CPA8(&lms[2*t], &maskp[b*NVERT+2*t]);
    if (t<4) CPA8(&Bws[2*t], &g_Bw[rbase+2*t]);
    #pragma unroll
    for (int j=0;j<32;j++){ int p=t+j*256, r=p>>5, c=(p&31)*2;
        CPA8(&stage[r*66+c], &g_wc[(b*NVERT+r)*64+c]); }   // wc half 0
    CPAC();
    if (t<64) s2s[t] = copysignf(0.495f, __ldg(&wl[t]));
    const float bl0  = __ldg(&bl[0]);
    const float invt = 1.0f/__ldg(&temp[0]);
    CPAW0(); __syncthreads();

    const int qt = t>>7;            // 0..1
    const int q0 = qt*4;
    const int vl = t&127;

    // ---- pass A: logits, two 256-v halves ----
    for (int h=0; h<2; h++){
        if (h==1){
            __syncthreads();
            #pragma unroll
            for (int j=0;j<32;j++){ int p=t+j*256, r=p>>5, c=(p&31)*2;
                CPA8(&stage[r*66+c], &g_wc[(b*NVERT+256+r)*64+c]); }
            CPAC(); CPAW0(); __syncthreads();
        }
        const ull* pc0 = (const ull*)&stage[ vl      *66];
        const ull* pc1 = (const ull*)&stage[(vl+128) *66];
        const ull* pq0 = (const ull*)&wqs[(q0+0)*66];
        const ull* pq1 = (const ull*)&wqs[(q0+1)*66];
        const ull* pq2 = (const ull*)&wqs[(q0+2)*66];
        const ull* pq3 = (const ull*)&wqs[(q0+3)*66];
        const ull* s2p = (const ull*)s2s;

        ull a[8] = {0,0,0,0,0,0,0,0};
        #pragma unroll 8
        for (int ep=0; ep<32; ep++){
            ull cA = pc0[ep], cB = pc1[ep], s = s2p[ep];
            ull w0 = pq0[ep], w1 = pq1[ep], w2 = pq2[ep], w3 = pq3[ep];
            a[0] = f2fma(s, f2add(cA,w0)&ABS2, a[0]);
            a[1] = f2fma(s, f2add(cB,w0)&ABS2, a[1]);
            a[2] = f2fma(s, f2add(cA,w1)&ABS2, a[2]);
            a[3] = f2fma(s, f2add(cB,w1)&ABS2, a[3]);
            a[4] = f2fma(s, f2add(cA,w2)&ABS2, a[4]);
            a[5] = f2fma(s, f2add(cB,w2)&ABS2, a[5]);
            a[6] = f2fma(s, f2add(cA,w3)&ABS2, a[6]);
            a[7] = f2fma(s, f2add(cB,w3)&ABS2, a[7]);
        }
        #pragma unroll
        for (int i=0;i<4;i++){
            #pragma unroll
            for (int j=0;j<2;j++){
                float2 f = funpack(a[i*2+j]);
                int vg = h*256 + (j? vl+128 : vl);
                float lg = 0.505f*(Aws[vg] + Bws[q0+i]) + bl0 + f.x + f.y;
                float lm = lms[vg];
                L[(q0+i)*512 + vg] = lg*invt*lm - 99999.f*(1.f-lm);
            }
        }
    }
    __syncthreads();

    // ---- pass B: softmax (warp w handles q-row w) ----
    {
        const int lane = t&31, w = t>>5;
        float lv[16];
        #pragma unroll
        for (int j=0;j<16;j++) lv[j] = L[w*512 + lane + 32*j];
        float mx = lv[0];
        #pragma unroll
        for (int j=1;j<16;j++) mx = fmaxf(mx, lv[j]);
        for (int off=16; off; off>>=1) mx = fmaxf(mx, __shfl_xor_sync(~0u, mx, off));
        float ev[16], ssum=0.f;
        #pragma unroll
        for (int j=0;j<16;j++){ ev[j] = __expf(lv[j]-mx); ssum += ev[j]; }
        for (int off=16; off; off>>=1) ssum += __shfl_xor_sync(~0u, ssum, off);
        float inv = 1.0f/ssum;
        #pragma unroll
        for (int j=0;j<16;j++) L[w*512 + lane + 32*j] = ev[j]*inv*lms[lane+32*j];
    }
    __syncthreads();

    // ---- pass C: heads = probs @ m. thread = (qg 4q's, sr 64-v range, ep) ----
    const int ep  = t&31;
    const int sr  = (t>>5)&3;
    const int qg  = t>>7;
    ull acc[4] = {0,0,0,0};

    for (int h=0; h<2; h++){
        #pragma unroll
        for (int j=0;j<32;j++){ int p=t+j*256, r=p>>5, c=(p&31)*2;
            CPA8(&stage[r*66+c], &g_m[(b*NVERT + h*256 + r)*64 + c]); }
        CPAC(); CPAW0(); __syncthreads();
        const float* L0 = &L[(qg*4+0)*512 + h*256 + sr*64];
        const float* L1 = &L[(qg*4+1)*512 + h*256 + sr*64];
        const float* L2 = &L[(qg*4+2)*512 + h*256 + sr*64];
        const float* L3 = &L[(qg*4+3)*512 + h*256 + sr*64];
        #pragma unroll 4
        for (int vv=0; vv<64; vv+=4){
            ull m0 = *(const ull*)&stage[(sr*64+vv+0)*66 + 2*ep];
            ull m1 = *(const ull*)&stage[(sr*64+vv+1)*66 + 2*ep];
            ull m2 = *(const ull*)&stage[(sr*64+vv+2)*66 + 2*ep];
            ull m3 = *(const ull*)&stage[(sr*64+vv+3)*66 + 2*ep];
            float4 p0 = *(const float4*)&L0[vv];
            float4 p1 = *(const float4*)&L1[vv];
            float4 p2 = *(const float4*)&L2[vv];
            float4 p3 = *(const float4*)&L3[vv];
            acc[0]=f2fma(fsplat(p0.x),m0,acc[0]); acc[0]=f2fma(fsplat(p0.y),m1,acc[0]);
            acc[0]=f2fma(fsplat(p0.z),m2,acc[0]); acc[0]=f2fma(fsplat(p0.w),m3,acc[0]);
            acc[1]=f2fma(fsplat(p1.x),m0,acc[1]); acc[1]=f2fma(fsplat(p1.y),m1,acc[1]);
            acc[1]=f2fma(fsplat(p1.z),m2,acc[1]); acc[1]=f2fma(fsplat(p1.w),m3,acc[1]);
            acc[2]=f2fma(fsplat(p2.x),m0,acc[2]); acc[2]=f2fma(fsplat(p2.y),m1,acc[2]);
            acc[2]=f2fma(fsplat(p2.z),m2,acc[2]); acc[2]=f2fma(fsplat(p2.w),m3,acc[2]);
            acc[3]=f2fma(fsplat(p3.x),m0,acc[3]); acc[3]=f2fma(fsplat(p3.y),m1,acc[3]);
            acc[3]=f2fma(fsplat(p3.z),m2,acc[3]); acc[3]=f2fma(fsplat(p3.w),m3,acc[3]);
        }
        __syncthreads();
    }
    #pragma unroll
    for (int i=0;i<4;i++) hpart[((sr*2+qg)*32+ep)*4+i] = acc[i];
    __syncthreads();

    // combine partials -> heads (lrelu), then stage Wr
    {
        const int tq = t>>5, tep = t&31;
        const int hqg = tq>>2, hi = tq&3;
        ull s = f2add(f2add(hpart[((0*2+hqg)*32+tep)*4+hi], hpart[((1*2+hqg)*32+tep)*4+hi]),
                      f2add(hpart[((2*2+hqg)*32+tep)*4+hi], hpart[((3*2+hqg)*32+tep)*4+hi]));
        float2 hv = funpack(s);
        heads[tq*66+2*tep]   = lrelu(hv.x);
        heads[tq*66+2*tep+1] = lrelu(hv.y);
    }
    #pragma unroll
    for (int j=0;j<8;j++){ int p=t+j*256, k=p>>5, c=(p&31)*2;
        CPA8(&stage[k*66+c], &Wr[k*64+c]); }
    CPAC(); CPAW0(); __syncthreads();

    // ---- final: out = lrelu(heads)@Wr + br + v2 ----
    {
        const int q = t>>5, c0 = (t&31)*2;
        ull oacc = 0;
        #pragma unroll 8
        for (int e=0; e<64; e++)
            oacc = f2fma(fsplat(heads[q*66+e]), *(const ull*)&stage[e*66+c0], oacc);
        float2 o = funpack(oacc);
        int row = rbase + q;
        float r0v = o.x + __ldg(&br[c0])   + v2s[q*64+c0];
        float r1v = o.y + __ldg(&br[c0+1]) + v2s[q*64+c0+1];
        *(float2*)&g_v[row*64+c0] = make_float2(r0v, r1v);
        if (dout) *(float2*)&dout[row*64+c0] = make_float2(r0v, r1v);
    }
}

// ---------------------------------------------------------------------------
extern "C" void kernel_launch(void* const* d_in, const int* in_sizes, int n_in,
                              void* d_out, int out_size)
{
    const float* vertices = (const float*)d_in[0];
    const float* mask     = (const float*)d_in[1];
    const float* W_embed  = (const float*)d_in[2];
    const float* b_embed  = (const float*)d_in[3];
    const float* W_mlp    = (const float*)d_in[4];
    const float* b_mlp    = (const float*)d_in[5];
    const float* W_qcm    = (const float*)d_in[6];
    const float* b_qcm    = (const float*)d_in[7];
    const float* W_ch     = (const float*)d_in[8];
    const float* b_ch     = (const float*)d_in[9];
    const float* W_logit  = (const float*)d_in[10];
    const float* b_logit  = (const float*)d_in[11];
    const float* W_red    = (const float*)d_in[12];
    const float* b_red    = (const float*)d_in[13];
    const float* temp     = (const float*)d_in[14];
    float* out = (float*)d_out;

    const int mlp_smem  = MLPS*4;
    const int attn_smem = ATTNS*4;
    cudaFuncSetAttribute(k_mlp,  cudaFuncAttributeMaxDynamicSharedMemorySize, mlp_smem);
    cudaFuncSetAttribute(k_attn, cudaFuncAttributeMaxDynamicSharedMemorySize, attn_smem);

    for (int i=0; i<3; i++){
        k_mlp<<<128,256,mlp_smem>>>(i==0 ? vertices : (const float*)nullptr, W_embed, b_embed,
                                    W_mlp + i*4096, b_mlp + i*64,
                                    W_qcm + i*12288, b_qcm + i*192,
                                    W_ch  + i*4096, b_ch  + i*64,
                                    W_logit + i*64);
        k_attn<<<dim3(64,NBATCH),256,attn_smem>>>(i==2 ? out : (float*)nullptr,
                                                  W_logit + i*64, b_logit + i,
                                                  W_red + i*4096, b_red + i*64,
                                                  temp + i, mask);
    }
}